// round 12
// baseline (speedup 1.0000x reference)
#include <cuda_runtime.h>
#include <cstdint>
#include <math.h>

#define NB 32
#define NS 512
#define NI 128
#define NH 128
#define NO 32
#define NG 384   // 3*H
#define NPROD 16             // producer CTAs (2 batches each)
#define NCONS 132            // consumer CTAs (148-16)
#define FLAG_STEP 8
#define NFLAG (NS / FLAG_STEP)

// Scratch (device globals; no allocation in kernel_launch)
__device__ float g_ih[(size_t)NB * NS * NG];          // [b][s][g]
__device__ float g_coef[(size_t)NS * NB * 4 * NH];    // [s*32+b][plane][j]
__device__ float g_wT[(size_t)NH * NG];               // [i][c] = W_hh[c][i]
__device__ unsigned g_flag[NFLAG];                    // per-8-step counters (0..16)

// ---------------- helpers ----------------
__device__ __forceinline__ float ex2f(float x) {
    float r; asm("ex2.approx.f32 %0, %1;" : "=f"(r) : "f"(x)); return r;
}
__device__ __forceinline__ float rcpf(float x) {
    float r; asm("rcp.approx.f32 %0, %1;" : "=f"(r) : "f"(x)); return r;
}
__device__ __forceinline__ float sigf(float x) {
    return rcpf(1.0f + ex2f(-1.4426950408889634f * x));
}
__device__ __forceinline__ float tanh_fast(float x) {
    float e = ex2f(2.8853900817779268f * x);   // e^{2x}
    return 1.0f - 2.0f * rcpf(e + 1.0f);
}
__device__ __forceinline__ unsigned long long pack2(float lo, float hi) {
    unsigned long long r;
    asm("mov.b64 %0, {%1,%2};" : "=l"(r)
        : "r"(__float_as_uint(lo)), "r"(__float_as_uint(hi)));
    return r;
}
__device__ __forceinline__ void unpack2(unsigned long long v, float& lo, float& hi) {
    unsigned a, b;
    asm("mov.b64 {%0,%1}, %2;" : "=r"(a), "=r"(b) : "l"(v));
    lo = __uint_as_float(a); hi = __uint_as_float(b);
}
__device__ __forceinline__ void ffma2(unsigned long long& acc,
                                      unsigned long long a, unsigned long long b) {
    asm("fma.rn.f32x2 %0, %1, %2, %0;" : "+l"(acc) : "l"(a), "l"(b));
}
__device__ __forceinline__ unsigned long long addf2(unsigned long long a,
                                                    unsigned long long b) {
    unsigned long long r;
    asm("add.rn.f32x2 %0, %1, %2;" : "=l"(r) : "l"(a), "l"(b));
    return r;
}
__device__ __forceinline__ unsigned ld_acquire(const unsigned* p) {
    unsigned v;
    asm volatile("ld.acquire.gpu.global.b32 %0, [%1];" : "=r"(v) : "l"(p));
    return v;
}
__device__ __forceinline__ void red_add_release(unsigned* p, unsigned v) {
    asm volatile("red.release.gpu.global.add.u32 [%0], %1;" :: "l"(p), "r"(v));
}

// ---------------- init: zero flags + transpose W_hh ----------------
__global__ void __launch_bounds__(256) init_kernel(const float* __restrict__ W_hh) {
    int t = blockIdx.x * 256 + threadIdx.x;
    if (t < NFLAG) g_flag[t] = 0u;
    for (int o = t; o < NH * NG; o += gridDim.x * 256) {
        int i = o / NG, c = o - i * NG;
        g_wT[o] = W_hh[(size_t)c * NH + i];
    }
}

// ---------------- Phase A: ih = x @ W_ih^T + b_ih ----------------
// CTA tile 128(m) x 64(n), 256 threads, K in 4 chunks of 32.
__global__ void __launch_bounds__(256) ih_gemm_kernel(
    const float* __restrict__ x, const float* __restrict__ W_ih,
    const float* __restrict__ b_ih)
{
    __shared__ __align__(16) float As[128 * 32];   // [m][k]
    __shared__ __align__(16) float Bs[32 * 64];    // [k][n]
    const int m0 = blockIdx.x * 128;
    const int n0 = blockIdx.y * 64;
    const int tid = threadIdx.x;
    const int tx = tid & 7;
    const int ty = tid >> 3;

    unsigned long long acc[4][4];
#pragma unroll
    for (int a = 0; a < 4; a++)
#pragma unroll
        for (int c = 0; c < 4; c++) acc[a][c] = 0ull;

    const float4* x4 = (const float4*)x;
    const float4* w4 = (const float4*)W_ih;
    const int lm = tid >> 3;
    const int lk = tid & 7;

    float4 ra[4], rb[2];
#define LOAD_CHUNK(kc)                                                          \
    {                                                                           \
        _Pragma("unroll")                                                       \
        for (int r = 0; r < 4; r++)                                             \
            ra[r] = x4[(size_t)(m0 + lm + r * 32) * 32 + (kc) * 8 + lk];        \
        _Pragma("unroll")                                                       \
        for (int r = 0; r < 2; r++) {                                           \
            int idx = tid + r * 256;                                            \
            rb[r] = w4[(size_t)(n0 + (idx >> 3)) * 32 + (kc) * 8 + (idx & 7)];  \
        }                                                                       \
    }

    LOAD_CHUNK(0);
#pragma unroll
    for (int kc = 0; kc < 4; kc++) {
        __syncthreads();
#pragma unroll
        for (int r = 0; r < 4; r++)
            ((float4*)As)[(lm + r * 32) * 8 + lk] = ra[r];
#pragma unroll
        for (int r = 0; r < 2; r++) {
            int idx = tid + r * 256;
            int n = idx >> 3, kq = idx & 7;
            Bs[(kq * 4 + 0) * 64 + n] = rb[r].x;
            Bs[(kq * 4 + 1) * 64 + n] = rb[r].y;
            Bs[(kq * 4 + 2) * 64 + n] = rb[r].z;
            Bs[(kq * 4 + 3) * 64 + n] = rb[r].w;
        }
        __syncthreads();
        if (kc < 3) LOAD_CHUNK(kc + 1);
#pragma unroll 8
        for (int k = 0; k < 32; k++) {
            unsigned long long a2[4];
#pragma unroll
            for (int mm = 0; mm < 4; mm++) {
                float av = As[(ty * 4 + mm) * 32 + k];
                a2[mm] = pack2(av, av);
            }
            const ulonglong2* bp = (const ulonglong2*)(Bs + k * 64 + tx * 8);
            ulonglong2 p0 = bp[0], p1 = bp[1];
            unsigned long long b2[4] = {p0.x, p0.y, p1.x, p1.y};
#pragma unroll
            for (int mm = 0; mm < 4; mm++)
#pragma unroll
                for (int c = 0; c < 4; c++)
                    ffma2(acc[mm][c], a2[mm], b2[c]);
        }
    }
#undef LOAD_CHUNK
#pragma unroll
    for (int mm = 0; mm < 4; mm++) {
        int m = m0 + ty * 4 + mm;
        float* orow = g_ih + (size_t)m * NG + n0 + tx * 8;
        float vals[8];
#pragma unroll
        for (int c = 0; c < 4; c++) {
            float lo, hi;
            unpack2(acc[mm][c], lo, hi);
            int n = n0 + tx * 8 + c * 2;
            vals[c * 2]     = lo + b_ih[n];
            vals[c * 2 + 1] = hi + b_ih[n + 1];
        }
        ((float4*)orow)[0] = make_float4(vals[0], vals[1], vals[2], vals[3]);
        ((float4*)orow)[1] = make_float4(vals[4], vals[5], vals[6], vals[7]);
    }
}

// ---------------- Mega kernel: dual-batch scan producers + jac consumers ----------------
__global__ void __launch_bounds__(384, 1) mega_kernel(
    const float* __restrict__ W_hh, const float* __restrict__ b_hh,
    const float* __restrict__ W_y,  const float* __restrict__ b_y,
    float* __restrict__ out)
{
    const int tid = threadIdx.x;

    if (blockIdx.x < NPROD) {
        // ============ PRODUCER: GRU scan for batches b0 and b0+16 ============
        const int b0 = blockIdx.x;
        const int b1 = b0 + 16;
        const int g = tid;
        const int role = g >> 7;        // 0: r, 1: z, 2: n (warp-uniform)
        const int j = g & 127;

        __shared__ __align__(16) float h_sh[2][NH];
        __shared__ __align__(8) float2 rp_sh[2][NH];
        __shared__ __align__(8) float2 zp_sh[2][NH];

        unsigned long long w2[64];
        const unsigned long long* wrow =
            (const unsigned long long*)(W_hh + (size_t)g * NH);
#pragma unroll
        for (int k2 = 0; k2 < 64; k2++) w2[k2] = wrow[k2];
        const float bh = b_hh[g];

        if (g < NH) { h_sh[0][g] = 0.0f; h_sh[1][g] = 0.0f; }

        const float* ihp0 = g_ih + (size_t)b0 * NS * NG;
        const float* ihp1 = g_ih + (size_t)b1 * NS * NG;
        float ihn0 = ihp0[g];
        float ihn1 = ihp1[g];
        __syncthreads();

        for (int s = 0; s < NS; s++) {
            float ihc0 = ihn0, ihc1 = ihn1;
            if (s + 1 < NS) {
                ihn0 = ihp0[(size_t)(s + 1) * NG + g];
                ihn1 = ihp1[(size_t)(s + 1) * NG + g];
            }

            // two interleaved matvecs sharing w2
            unsigned long long a00 = 0ull, a01 = 0ull, a10 = 0ull, a11 = 0ull;
            const ulonglong2* h40 = (const ulonglong2*)h_sh[0];
            const ulonglong2* h41 = (const ulonglong2*)h_sh[1];
#pragma unroll
            for (int k4 = 0; k4 < 32; k4++) {
                ulonglong2 u0 = h40[k4];
                ulonglong2 u1 = h41[k4];
                ffma2(a00, w2[2 * k4],     u0.x);
                ffma2(a01, w2[2 * k4 + 1], u0.y);
                ffma2(a10, w2[2 * k4],     u1.x);
                ffma2(a11, w2[2 * k4 + 1], u1.y);
            }
            unsigned long long t0 = addf2(a00, a01);
            unsigned long long t1 = addf2(a10, a11);
            float l0, h0, l1, h1;
            unpack2(t0, l0, h0);
            unpack2(t1, l1, h1);
            float sum0 = l0 + h0 + bh;
            float sum1 = l1 + h1 + bh;

            const size_t cb0 = ((size_t)(s * NB + b0)) * (4 * NH);
            const size_t cb1 = ((size_t)(s * NB + b1)) * (4 * NH);
            if (role == 0) {
                float r0 = sigf(ihc0 + sum0);
                float r1 = sigf(ihc1 + sum1);
                rp_sh[0][j] = make_float2(r0, r0 * (1.0f - r0));
                rp_sh[1][j] = make_float2(r1, r1 * (1.0f - r1));
                asm volatile("bar.arrive 1, 384;" ::: "memory");
            } else if (role == 1) {
                float z0 = sigf(ihc0 + sum0);
                float z1 = sigf(ihc1 + sum1);
                zp_sh[0][j] = make_float2(z0, z0 * (1.0f - z0));
                zp_sh[1][j] = make_float2(z1, z1 * (1.0f - z1));
                g_coef[cb0 + 3 * NH + j] = z0;
                g_coef[cb1 + 3 * NH + j] = z1;
                asm volatile("bar.arrive 1, 384;" ::: "memory");
            } else {
                float M0 = sum0, M1 = sum1;
                float hp0 = h_sh[0][j];
                float hp1 = h_sh[1][j];
                asm volatile("bar.sync 1, 384;" ::: "memory");
                float2 rp0 = rp_sh[0][j], rp1 = rp_sh[1][j];
                float2 zp0 = zp_sh[0][j], zp1 = zp_sh[1][j];
                float n0 = tanh_fast(ihc0 + rp0.x * M0);
                float n1 = tanh_fast(ihc1 + rp1.x * M1);
                float c670 = (1.0f - n0 * n0) * (1.0f - zp0.x);
                float c671 = (1.0f - n1 * n1) * (1.0f - zp1.x);
                g_coef[cb0 + j]          = rp0.y * M0 * c670;
                g_coef[cb0 + NH + j]     = rp0.x * c670;
                g_coef[cb0 + 2 * NH + j] = zp0.y * (hp0 - n0);
                g_coef[cb1 + j]          = rp1.y * M1 * c671;
                g_coef[cb1 + NH + j]     = rp1.x * c671;
                g_coef[cb1 + 2 * NH + j] = zp1.y * (hp1 - n1);
                h_sh[0][j] = n0 + zp0.x * (hp0 - n0);
                h_sh[1][j] = n1 + zp1.x * (hp1 - n1);
            }
            __syncthreads();
            if (tid == 0 && (s & (FLAG_STEP - 1)) == FLAG_STEP - 1)
                red_add_release(&g_flag[s >> 3], 1u);
        }

        // y = h_last @ W_y^T + b_y (both batches)
        if (g < NO) {
            float a0 = b_y[g], a1 = b_y[g];
            const float* wy = W_y + (size_t)g * NH;
#pragma unroll
            for (int k = 0; k < NH; k++) {
                float w = wy[k];
                a0 = fmaf(w, h_sh[0][k], a0);
                a1 = fmaf(w, h_sh[1][k], a1);
            }
            out[b0 * NO + g] = a0;
            out[b1 * NO + g] = a1;
        }
    } else {
        // ========== CONSUMER: Jacobian, dual-b tiles (W loaded once/pair) ==========
        const int c0 = blockIdx.x - NPROD;  // 0..131
        const int w = tid >> 5;             // warp 0..11 -> i rows
        const int lane = tid & 31;
        const int j0 = lane * 4;
        float* jac = out + NB * NO;

        int scready = -1;
        for (int t = c0; t < NS * 16; t += NCONS) {
            int s = t >> 4;
            int b0 = t & 15;                // pair: (s, b0) and (s, b0+16)
            int sc = s >> 3;
            if (sc != scready) {
                if (tid == 0) {
                    while (ld_acquire(&g_flag[sc]) < (unsigned)NPROD) __nanosleep(128);
                }
                __syncthreads();
                scready = sc;
            }
            const float4* cpA = (const float4*)(g_coef + (size_t)(s * NB + b0) * (4 * NH));
            const float4* cpB = (const float4*)(g_coef + (size_t)(s * NB + b0 + 16) * (4 * NH));
            float4 crA = cpA[lane], cnA = cpA[32 + lane], czA = cpA[64 + lane], zzA = cpA[96 + lane];
            float4 crB = cpB[lane], cnB = cpB[32 + lane], czB = cpB[64 + lane], zzB = cpB[96 + lane];
            float* obA = jac + ((size_t)((NS - 1 - s) * NB + b0)) * (NH * NH);
            float* obB = jac + ((size_t)((NS - 1 - s) * NB + b0 + 16)) * (NH * NH);
            for (int i = w; i < NH; i += 12) {
                const float4* wp = (const float4*)(g_wT + (size_t)i * NG);
                float4 wr = wp[lane];          // W_hh[j, i]
                float4 wz = wp[32 + lane];     // W_hh[H+j, i]
                float4 wn = wp[64 + lane];     // W_hh[2H+j, i]
                float4 vA, vB;
                vA.x = fmaf(wr.x, crA.x, fmaf(wn.x, cnA.x, wz.x * czA.x));
                vA.y = fmaf(wr.y, crA.y, fmaf(wn.y, cnA.y, wz.y * czA.y));
                vA.z = fmaf(wr.z, crA.z, fmaf(wn.z, cnA.z, wz.z * czA.z));
                vA.w = fmaf(wr.w, crA.w, fmaf(wn.w, cnA.w, wz.w * czA.w));
                vB.x = fmaf(wr.x, crB.x, fmaf(wn.x, cnB.x, wz.x * czB.x));
                vB.y = fmaf(wr.y, crB.y, fmaf(wn.y, cnB.y, wz.y * czB.y));
                vB.z = fmaf(wr.z, crB.z, fmaf(wn.z, cnB.z, wz.z * czB.z));
                vB.w = fmaf(wr.w, crB.w, fmaf(wn.w, cnB.w, wz.w * czB.w));
                if ((i >> 2) == lane) {        // diagonal j == i
                    int d = i & 3;
                    if (d == 0) { vA.x += zzA.x; vB.x += zzB.x; }
                    else if (d == 1) { vA.y += zzA.y; vB.y += zzB.y; }
                    else if (d == 2) { vA.z += zzA.z; vB.z += zzB.z; }
                    else { vA.w += zzA.w; vB.w += zzB.w; }
                }
                *(float4*)(obA + i * NH + j0) = vA;
                *(float4*)(obB + i * NH + j0) = vB;
            }
        }
    }
}

// ---------------- launch ----------------
extern "C" void kernel_launch(void* const* d_in, const int* in_sizes, int n_in,
                              void* d_out, int out_size) {
    const float* x    = (const float*)d_in[0];
    const float* W_ih = (const float*)d_in[1];
    const float* W_hh = (const float*)d_in[2];
    const float* b_ih = (const float*)d_in[3];
    const float* b_hh = (const float*)d_in[4];
    const float* W_y  = (const float*)d_in[5];
    const float* b_y  = (const float*)d_in[6];
    float* out = (float*)d_out;

    init_kernel<<<64, 256>>>(W_hh);
    ih_gemm_kernel<<<dim3(128, 6), 256>>>(x, W_ih, b_ih);
    mega_kernel<<<NPROD + NCONS, NG>>>(W_hh, b_hh, W_y, b_y, out);
}

// round 14
// speedup vs baseline: 2.0379x; 2.0379x over previous
#include <cuda_runtime.h>
#include <cstdint>
#include <math.h>

#define NB 32
#define NS 512
#define NI 128
#define NH 128
#define NO 32
#define NG 384   // 3*H
#define NCONS 116            // consumer CTAs in mega kernel (148-32)
#define FLAG_STEP 8
#define NFLAG (NS / FLAG_STEP)

// Scratch (device globals; no allocation in kernel_launch)
__device__ float g_ih[(size_t)NB * NS * NG];          // [b][s][g]
__device__ float g_coef[(size_t)NS * NB * 4 * NH];    // [s*32+b][plane][j]
__device__ float g_wT[(size_t)NH * NG];               // [i][c] = W_hh[c][i]
__device__ unsigned g_flag[NFLAG];                    // per-8-step completion counters

// ---------------- helpers ----------------
__device__ __forceinline__ float ex2f(float x) {
    float r; asm("ex2.approx.f32 %0, %1;" : "=f"(r) : "f"(x)); return r;
}
__device__ __forceinline__ float rcpf(float x) {
    float r; asm("rcp.approx.f32 %0, %1;" : "=f"(r) : "f"(x)); return r;
}
__device__ __forceinline__ float sigf(float x) {
    return rcpf(1.0f + ex2f(-1.4426950408889634f * x));
}
__device__ __forceinline__ float tanh_fast(float x) {
    float e = ex2f(2.8853900817779268f * x);   // e^{2x}
    return 1.0f - 2.0f * rcpf(e + 1.0f);
}
__device__ __forceinline__ unsigned long long pack2(float lo, float hi) {
    unsigned long long r;
    asm("mov.b64 %0, {%1,%2};" : "=l"(r)
        : "r"(__float_as_uint(lo)), "r"(__float_as_uint(hi)));
    return r;
}
__device__ __forceinline__ void unpack2(unsigned long long v, float& lo, float& hi) {
    unsigned a, b;
    asm("mov.b64 {%0,%1}, %2;" : "=r"(a), "=r"(b) : "l"(v));
    lo = __uint_as_float(a); hi = __uint_as_float(b);
}
__device__ __forceinline__ void ffma2(unsigned long long& acc,
                                      unsigned long long a, unsigned long long b) {
    asm("fma.rn.f32x2 %0, %1, %2, %0;" : "+l"(acc) : "l"(a), "l"(b));
}
__device__ __forceinline__ unsigned long long addf2(unsigned long long a,
                                                    unsigned long long b) {
    unsigned long long r;
    asm("add.rn.f32x2 %0, %1, %2;" : "=l"(r) : "l"(a), "l"(b));
    return r;
}
__device__ __forceinline__ unsigned ld_acquire(const unsigned* p) {
    unsigned v;
    asm volatile("ld.acquire.gpu.global.b32 %0, [%1];" : "=r"(v) : "l"(p));
    return v;
}
__device__ __forceinline__ void red_add_release(unsigned* p, unsigned v) {
    asm volatile("red.release.gpu.global.add.u32 [%0], %1;" :: "l"(p), "r"(v));
}

// ---------------- init: zero flags + transpose W_hh ----------------
__global__ void __launch_bounds__(256) init_kernel(const float* __restrict__ W_hh) {
    int t = blockIdx.x * 256 + threadIdx.x;
    if (t < NFLAG) g_flag[t] = 0u;
    for (int o = t; o < NH * NG; o += gridDim.x * 256) {
        int i = o / NG, c = o - i * NG;
        g_wT[o] = W_hh[(size_t)c * NH + i];
    }
}

// ---------------- Phase A: ih = x @ W_ih^T + b_ih ----------------
// CTA tile 128(m) x 128(n), 256 threads, thread = 4m x 16n (73% FFMA2 density).
// K in 4 chunks of 32, register double-buffered global loads.
__global__ void __launch_bounds__(256) ih_gemm_kernel(
    const float* __restrict__ x, const float* __restrict__ W_ih,
    const float* __restrict__ b_ih)
{
    __shared__ __align__(16) float As[128 * 32];   // [m][k] 16 KB
    __shared__ __align__(16) float Bs[32 * 128];   // [k][n] 16 KB
    const int m0 = blockIdx.x * 128;
    const int n0 = blockIdx.y * 128;
    const int tid = threadIdx.x;
    const int tx = tid & 7;      // n-group: n = tx*16 .. tx*16+15
    const int ty = tid >> 3;     // 0..31: m rows ty*4 .. ty*4+3

    unsigned long long acc[4][8];
#pragma unroll
    for (int a = 0; a < 4; a++)
#pragma unroll
        for (int c = 0; c < 8; c++) acc[a][c] = 0ull;

    const float4* x4 = (const float4*)x;
    const float4* w4 = (const float4*)W_ih;
    const int lm = tid >> 3;     // 0..31
    const int lk = tid & 7;      // 0..7

    float4 ra[4], rb[4];
#define LOAD_CHUNK(kc)                                                          \
    {                                                                           \
        _Pragma("unroll")                                                       \
        for (int r = 0; r < 4; r++)                                             \
            ra[r] = x4[(size_t)(m0 + lm + r * 32) * 32 + (kc) * 8 + lk];        \
        _Pragma("unroll")                                                       \
        for (int r = 0; r < 4; r++)                                             \
            rb[r] = w4[(size_t)(n0 + lm + r * 32) * 32 + (kc) * 8 + lk];        \
    }

    LOAD_CHUNK(0);
#pragma unroll
    for (int kc = 0; kc < 4; kc++) {
        __syncthreads();
        // As [m][k]: direct float4 copy
#pragma unroll
        for (int r = 0; r < 4; r++)
            ((float4*)As)[(lm + r * 32) * 8 + lk] = ra[r];
        // Bs: transpose to [k][n]
#pragma unroll
        for (int r = 0; r < 4; r++) {
            int n = lm + r * 32;
            Bs[(lk * 4 + 0) * 128 + n] = rb[r].x;
            Bs[(lk * 4 + 1) * 128 + n] = rb[r].y;
            Bs[(lk * 4 + 2) * 128 + n] = rb[r].z;
            Bs[(lk * 4 + 3) * 128 + n] = rb[r].w;
        }
        __syncthreads();
        if (kc < 3) LOAD_CHUNK(kc + 1);
#pragma unroll 4
        for (int k = 0; k < 32; k++) {
            unsigned long long a2[4];
#pragma unroll
            for (int mm = 0; mm < 4; mm++) {
                float av = As[(ty * 4 + mm) * 32 + k];
                a2[mm] = pack2(av, av);
            }
            const ulonglong2* bp = (const ulonglong2*)(Bs + k * 128 + tx * 16);
            ulonglong2 p0 = bp[0], p1 = bp[1], p2 = bp[2], p3 = bp[3];
            unsigned long long b2[8] = {p0.x, p0.y, p1.x, p1.y,
                                        p2.x, p2.y, p3.x, p3.y};
#pragma unroll
            for (int mm = 0; mm < 4; mm++)
#pragma unroll
                for (int c = 0; c < 8; c++)
                    ffma2(acc[mm][c], a2[mm], b2[c]);
        }
    }
#undef LOAD_CHUNK
    // Epilogue: bias + store 16 contiguous floats per (thread, m-row)
#pragma unroll
    for (int mm = 0; mm < 4; mm++) {
        int m = m0 + ty * 4 + mm;
        float* orow = g_ih + (size_t)m * NG + n0 + tx * 16;
#pragma unroll
        for (int q = 0; q < 4; q++) {
            float lo0, hi0, lo1, hi1;
            unpack2(acc[mm][2 * q], lo0, hi0);
            unpack2(acc[mm][2 * q + 1], lo1, hi1);
            int n = n0 + tx * 16 + q * 4;
            ((float4*)orow)[q] = make_float4(lo0 + b_ih[n],
                                             hi0 + b_ih[n + 1],
                                             lo1 + b_ih[n + 2],
                                             hi1 + b_ih[n + 3]);
        }
    }
}

// ---------------- Mega kernel: scan producers + jac consumers (R10 verbatim) ----------------
__global__ void __launch_bounds__(384, 1) mega_kernel(
    const float* __restrict__ W_hh, const float* __restrict__ b_hh,
    const float* __restrict__ W_y,  const float* __restrict__ b_y,
    float* __restrict__ out)
{
    const int tid = threadIdx.x;

    if (blockIdx.x < NB) {
        // ================= PRODUCER: GRU scan for batch b =================
        const int b = blockIdx.x;
        const int g = tid;
        const int role = g >> 7;        // 0: r, 1: z, 2: n (warp-uniform)
        const int j = g & 127;

        __shared__ __align__(16) float h_sh[NH];
        __shared__ __align__(8) float2 rp_sh[NH];   // (r, r*(1-r))
        __shared__ __align__(8) float2 zp_sh[NH];   // (z, z*(1-z))

        unsigned long long w2[64];
        const unsigned long long* wrow =
            (const unsigned long long*)(W_hh + (size_t)g * NH);
#pragma unroll
        for (int k2 = 0; k2 < 64; k2++) w2[k2] = wrow[k2];
        const float bh = b_hh[g];

        if (g < NH) h_sh[g] = 0.0f;

        const float* ihp = g_ih + (size_t)b * NS * NG;
        float ih_next = ihp[g];
        __syncthreads();

        for (int s = 0; s < NS; s++) {
            float ih_cur = ih_next;
            if (s + 1 < NS) ih_next = ihp[(size_t)(s + 1) * NG + g];

            // hh[g] = W_hh[g,:] . h + b_hh[g]  (f32x2)
            unsigned long long acc[4] = {0ull, 0ull, 0ull, 0ull};
            const ulonglong2* h4 = (const ulonglong2*)h_sh;
#pragma unroll
            for (int k4 = 0; k4 < 32; k4++) {
                ulonglong2 hv = h4[k4];
                ffma2(acc[(2 * k4) & 3],     w2[2 * k4],     hv.x);
                ffma2(acc[(2 * k4 + 1) & 3], w2[2 * k4 + 1], hv.y);
            }
            unsigned long long t01 = addf2(acc[0], acc[1]);
            unsigned long long t23 = addf2(acc[2], acc[3]);
            unsigned long long tt  = addf2(t01, t23);
            float lo, hi;
            unpack2(tt, lo, hi);
            float sum = lo + hi + bh;

            const size_t cb = ((size_t)(s * NB + b)) * (4 * NH);
            if (role == 0) {
                float r = sigf(ih_cur + sum);
                rp_sh[j] = make_float2(r, r * (1.0f - r));
                asm volatile("bar.arrive 1, 384;" ::: "memory");
            } else if (role == 1) {
                float z = sigf(ih_cur + sum);
                zp_sh[j] = make_float2(z, z * (1.0f - z));
                g_coef[cb + 3 * NH + j] = z;
                asm volatile("bar.arrive 1, 384;" ::: "memory");
            } else {
                float M = sum;
                float hp = h_sh[j];                 // own slot, pre-sync safe
                asm volatile("bar.sync 1, 384;" ::: "memory");
                float2 rp = rp_sh[j];
                float2 zp = zp_sh[j];
                float n = tanh_fast(ih_cur + rp.x * M);
                float c67 = (1.0f - n * n) * (1.0f - zp.x);
                g_coef[cb + j]          = rp.y * M * c67;     // cr
                g_coef[cb + NH + j]     = rp.x * c67;         // cn
                g_coef[cb + 2 * NH + j] = zp.y * (hp - n);    // cz
                h_sh[j] = n + zp.x * (hp - n);                // h_new
            }
            __syncthreads();
            // coef stores happen-before this bar; red.release gives consumers'
            // acquire loads transitive visibility (no MEMBAR needed).
            if (tid == 0 && (s & (FLAG_STEP - 1)) == FLAG_STEP - 1)
                red_add_release(&g_flag[s >> 3], 1u);
        }

        // y = h_last @ W_y^T + b_y
        if (g < NO) {
            float a = b_y[g];
            const float* wy = W_y + (size_t)g * NH;
#pragma unroll
            for (int k = 0; k < NH; k++) a = fmaf(wy[k], h_sh[k], a);
            out[b * NO + g] = a;
        }
    } else {
        // ========== CONSUMER: Jacobian, dual-b tiles (W loaded once/pair) ==========
        const int c0 = blockIdx.x - NB;     // 0..115
        const int w = tid >> 5;             // warp 0..11 -> i rows
        const int lane = tid & 31;
        const int j0 = lane * 4;
        float* jac = out + NB * NO;

        int scready = -1;
        for (int t = c0; t < NS * 16; t += NCONS) {
            int s = t >> 4;
            int b0 = t & 15;                // pair: (s, b0) and (s, b0+16)
            int sc = s >> 3;
            if (sc != scready) {
                if (tid == 0) {
                    while (ld_acquire(&g_flag[sc]) < (unsigned)NB) __nanosleep(128);
                }
                __syncthreads();
                scready = sc;
            }
            const float4* cpA = (const float4*)(g_coef + (size_t)(s * NB + b0) * (4 * NH));
            const float4* cpB = (const float4*)(g_coef + (size_t)(s * NB + b0 + 16) * (4 * NH));
            float4 crA = cpA[lane], cnA = cpA[32 + lane], czA = cpA[64 + lane], zzA = cpA[96 + lane];
            float4 crB = cpB[lane], cnB = cpB[32 + lane], czB = cpB[64 + lane], zzB = cpB[96 + lane];
            float* obA = jac + ((size_t)((NS - 1 - s) * NB + b0)) * (NH * NH);
            float* obB = jac + ((size_t)((NS - 1 - s) * NB + b0 + 16)) * (NH * NH);
            for (int i = w; i < NH; i += 12) {
                const float4* wp = (const float4*)(g_wT + (size_t)i * NG);
                float4 wr = wp[lane];          // W_hh[j, i]
                float4 wz = wp[32 + lane];     // W_hh[H+j, i]
                float4 wn = wp[64 + lane];     // W_hh[2H+j, i]
                float4 vA, vB;
                vA.x = fmaf(wr.x, crA.x, fmaf(wn.x, cnA.x, wz.x * czA.x));
                vA.y = fmaf(wr.y, crA.y, fmaf(wn.y, cnA.y, wz.y * czA.y));
                vA.z = fmaf(wr.z, crA.z, fmaf(wn.z, cnA.z, wz.z * czA.z));
                vA.w = fmaf(wr.w, crA.w, fmaf(wn.w, cnA.w, wz.w * czA.w));
                vB.x = fmaf(wr.x, crB.x, fmaf(wn.x, cnB.x, wz.x * czB.x));
                vB.y = fmaf(wr.y, crB.y, fmaf(wn.y, cnB.y, wz.y * czB.y));
                vB.z = fmaf(wr.z, crB.z, fmaf(wn.z, cnB.z, wz.z * czB.z));
                vB.w = fmaf(wr.w, crB.w, fmaf(wn.w, cnB.w, wz.w * czB.w));
                if ((i >> 2) == lane) {        // diagonal j == i
                    int d = i & 3;
                    if (d == 0) { vA.x += zzA.x; vB.x += zzB.x; }
                    else if (d == 1) { vA.y += zzA.y; vB.y += zzB.y; }
                    else if (d == 2) { vA.z += zzA.z; vB.z += zzB.z; }
                    else { vA.w += zzA.w; vB.w += zzB.w; }
                }
                *(float4*)(obA + i * NH + j0) = vA;
                *(float4*)(obB + i * NH + j0) = vB;
            }
        }
    }
}

// ---------------- launch ----------------
extern "C" void kernel_launch(void* const* d_in, const int* in_sizes, int n_in,
                              void* d_out, int out_size) {
    const float* x    = (const float*)d_in[0];
    const float* W_ih = (const float*)d_in[1];
    const float* W_hh = (const float*)d_in[2];
    const float* b_ih = (const float*)d_in[3];
    const float* b_hh = (const float*)d_in[4];
    const float* W_y  = (const float*)d_in[5];
    const float* b_y  = (const float*)d_in[6];
    float* out = (float*)d_out;

    init_kernel<<<64, 256>>>(W_hh);
    ih_gemm_kernel<<<dim3(128, 3), 256>>>(x, W_ih, b_ih);
    mega_kernel<<<NB + NCONS, NG>>>(W_hh, b_hh, W_y, b_y, out);
}